// round 1
// baseline (speedup 1.0000x reference)
#include <cuda_runtime.h>
#include <cuda_bf16.h>
#include <math.h>

#define NNODES 4096
#define MAXDEG 256
#define ALPHA  0.2f

// ---------------- scratch (no allocations allowed) ----------------
__device__ int   g_cnt[NNODES];
__device__ int   g_idx[NNODES * MAXDEG];
__device__ float g_h1 [8 * NNODES * 64];   // layer1 per-head features [hd][n][64]
__device__ float g_s1a[8 * NNODES];
__device__ float g_s2a[8 * NNODES];
__device__ float g_x2 [NNODES * 512];      // elu(hp) reshaped [n][hd*64+d]
__device__ float g_h2 [NNODES * 64];
__device__ float g_s1b[NNODES];
__device__ float g_s2b[NNODES];

__device__ __forceinline__ float lrelu(float x) { return x > 0.f ? x : ALPHA * x; }

// ---------------- CSR build: one block per row ----------------
__global__ void build_csr(const float* __restrict__ adj, int* __restrict__ cnt,
                          int* __restrict__ idx) {
    int row = blockIdx.x;
    __shared__ int s_idx[MAXDEG];
    __shared__ int s_cnt;
    if (threadIdx.x == 0) s_cnt = 0;
    __syncthreads();
    const float* r = adj + (size_t)row * NNODES;
    for (int c = threadIdx.x; c < NNODES; c += blockDim.x) {
        if (r[c] > 0.f) {
            int p = atomicAdd(&s_cnt, 1);
            if (p < MAXDEG) s_idx[p] = c;
        }
    }
    __syncthreads();
    int n = min(s_cnt, MAXDEG);
    if (threadIdx.x == 0) cnt[row] = n;
    for (int i = threadIdx.x; i < n; i += blockDim.x) idx[row * MAXDEG + i] = s_idx[i];
}

// ---------------- SGEMM, N fixed = 64, batched over blockIdx.z ----------------
// C[b] = A @ B[b];  A: [M,K] row-major (shared across batch), B: [K,64], C: [M,64]
#define BK 16
__global__ void gemm_n64(const float* __restrict__ A, const float* __restrict__ B,
                         float* __restrict__ C, int M, int K,
                         size_t strideB, size_t strideC) {
    __shared__ float As[BK][68];   // padded: 68 floats = 17 float4, keeps 16B align
    __shared__ float Bs[BK][68];
    int m0 = blockIdx.x * 64;
    const float* Bb = B + (size_t)blockIdx.z * strideB;
    float*       Cb = C + (size_t)blockIdx.z * strideC;
    int tid = threadIdx.x;
    int tx = tid & 15, ty = tid >> 4;
    float c[4][4] = {};

    for (int k0 = 0; k0 < K; k0 += BK) {
        #pragma unroll
        for (int p = 0; p < 4; p++) {
            int mm = (tid >> 4) + p * 16;
            int kk = tid & 15;
            As[kk][mm] = A[(size_t)(m0 + mm) * K + k0 + kk];
        }
        #pragma unroll
        for (int p = 0; p < 4; p++) {
            int kk = (tid >> 6) + p * 4;
            int nn = tid & 63;
            Bs[kk][nn] = Bb[(size_t)(k0 + kk) * 64 + nn];
        }
        __syncthreads();
        #pragma unroll
        for (int k = 0; k < BK; k++) {
            float4 a4 = *(const float4*)&As[k][ty * 4];
            float4 b4 = *(const float4*)&Bs[k][tx * 4];
            c[0][0] += a4.x * b4.x; c[0][1] += a4.x * b4.y; c[0][2] += a4.x * b4.z; c[0][3] += a4.x * b4.w;
            c[1][0] += a4.y * b4.x; c[1][1] += a4.y * b4.y; c[1][2] += a4.y * b4.z; c[1][3] += a4.y * b4.w;
            c[2][0] += a4.z * b4.x; c[2][1] += a4.z * b4.y; c[2][2] += a4.z * b4.z; c[2][3] += a4.z * b4.w;
            c[3][0] += a4.w * b4.x; c[3][1] += a4.w * b4.y; c[3][2] += a4.w * b4.z; c[3][3] += a4.w * b4.w;
        }
        __syncthreads();
    }
    #pragma unroll
    for (int i = 0; i < 4; i++) {
        float4 v = make_float4(c[i][0], c[i][1], c[i][2], c[i][3]);
        *(float4*)&Cb[(size_t)(m0 + ty * 4 + i) * 64 + tx * 4] = v;
    }
}

// ---------------- per-node attention scores: s1 = h.a1, s2 = h.a2 ----------------
// h: [HN][64] (head-major rows), a: [H][128] -> a1 = a[hd][0:64], a2 = a[hd][64:128]
__global__ void scores(const float* __restrict__ h, const float* __restrict__ a,
                       float* __restrict__ s1, float* __restrict__ s2, int HN) {
    int t = blockIdx.x * blockDim.x + threadIdx.x;
    if (t >= HN) return;
    int hd = t / NNODES;
    const float* hr = h + (size_t)t * 64;
    const float* a1 = a + hd * 128;
    const float* a2 = a1 + 64;
    float x1 = 0.f, x2 = 0.f;
    #pragma unroll
    for (int d = 0; d < 64; d++) { float v = hr[d]; x1 += v * a1[d]; x2 += v * a2[d]; }
    s1[t] = x1;
    s2[t] = x2;
}

// ---------------- sparse masked-softmax attention ----------------
// block = (row, head), 64 threads (thread = output channel d)
template <bool DO_ELU, bool LAYER1>
__global__ void att_kernel(const float* __restrict__ h, const float* __restrict__ s1,
                           const float* __restrict__ s2, const int* __restrict__ cnt,
                           const int* __restrict__ idx, float* __restrict__ out) {
    int row = blockIdx.x;
    int hd  = blockIdx.y;
    int tid = threadIdx.x;

    __shared__ int   s_nbr[MAXDEG];
    __shared__ float s_w[MAXDEG];
    __shared__ float s_red[2];

    int n = cnt[row];
    const int* ip = idx + row * MAXDEG;
    for (int i = tid; i < n; i += 64) s_nbr[i] = ip[i];
    __syncthreads();

    const float* s2h = s2 + (size_t)hd * NNODES;
    float s1i = s1[(size_t)hd * NNODES + row];

    // row max: lrelu monotone => max e = lrelu(s1i + max s2)
    float mx = -3.0e38f;
    for (int i = tid; i < n; i += 64) mx = fmaxf(mx, s2h[s_nbr[i]]);
    #pragma unroll
    for (int o = 16; o > 0; o >>= 1) mx = fmaxf(mx, __shfl_xor_sync(0xffffffffu, mx, o));
    if ((tid & 31) == 0) s_red[tid >> 5] = mx;
    __syncthreads();
    mx = fmaxf(s_red[0], s_red[1]);
    float m = lrelu(s1i + mx);
    __syncthreads();   // protect s_red reuse

    // weights + Z
    float zp = 0.f;
    for (int i = tid; i < n; i += 64) {
        float e = lrelu(s1i + s2h[s_nbr[i]]);
        float w = __expf(e - m);
        s_w[i] = w;
        zp += w;
    }
    #pragma unroll
    for (int o = 16; o > 0; o >>= 1) zp += __shfl_xor_sync(0xffffffffu, zp, o);
    if ((tid & 31) == 0) s_red[tid >> 5] = zp;
    __syncthreads();
    float Z = s_red[0] + s_red[1];

    // gather-accumulate: acc_d = sum_j w_j * h[j][d]
    const float* hh = h + (size_t)hd * NNODES * 64;
    float acc = 0.f;
    int i = 0;
    for (; i + 4 <= n; i += 4) {
        float v0 = hh[(size_t)s_nbr[i + 0] * 64 + tid];
        float v1 = hh[(size_t)s_nbr[i + 1] * 64 + tid];
        float v2 = hh[(size_t)s_nbr[i + 2] * 64 + tid];
        float v3 = hh[(size_t)s_nbr[i + 3] * 64 + tid];
        acc += s_w[i + 0] * v0;
        acc += s_w[i + 1] * v1;
        acc += s_w[i + 2] * v2;
        acc += s_w[i + 3] * v3;
    }
    for (; i < n; i++) acc += s_w[i] * hh[(size_t)s_nbr[i] * 64 + tid];

    float o = acc / Z;
    if (DO_ELU) o = (o > 0.f) ? o : expm1f(o);
    if (LAYER1) out[(size_t)row * 512 + hd * 64 + tid] = o;
    else        out[(size_t)row * 64 + tid] = o;
}

// ---------------- launcher ----------------
extern "C" void kernel_launch(void* const* d_in, const int* in_sizes, int n_in,
                              void* d_out, int out_size) {
    const float* features = (const float*)d_in[0];   // [4096, 256]
    const float* adj      = (const float*)d_in[1];   // [4096, 4096]
    const float* W_heads  = (const float*)d_in[2];   // [8, 256, 64]
    const float* a_heads  = (const float*)d_in[3];   // [8, 128, 1]
    const float* W_out    = (const float*)d_in[4];   // [512, 64]
    const float* a_out    = (const float*)d_in[5];   // [128, 1]
    float* out = (float*)d_out;                      // [4096, 64]

    int   *cnt, *idxp;
    float *h1, *s1a, *s2a, *x2, *h2, *s1b, *s2b;
    cudaGetSymbolAddress((void**)&cnt,  g_cnt);
    cudaGetSymbolAddress((void**)&idxp, g_idx);
    cudaGetSymbolAddress((void**)&h1,   g_h1);
    cudaGetSymbolAddress((void**)&s1a,  g_s1a);
    cudaGetSymbolAddress((void**)&s2a,  g_s2a);
    cudaGetSymbolAddress((void**)&x2,   g_x2);
    cudaGetSymbolAddress((void**)&h2,   g_h2);
    cudaGetSymbolAddress((void**)&s1b,  g_s1b);
    cudaGetSymbolAddress((void**)&s2b,  g_s2b);

    // 1. adjacency -> CSR
    build_csr<<<NNODES, 256>>>(adj, cnt, idxp);

    // 2. layer1 GEMM: h1[hd] = features @ W_heads[hd]
    gemm_n64<<<dim3(64, 1, 8), 256>>>(features, W_heads, h1, NNODES, 256,
                                      (size_t)256 * 64, (size_t)NNODES * 64);

    // 3. layer1 scores
    scores<<<(8 * NNODES) / 256, 256>>>(h1, a_heads, s1a, s2a, 8 * NNODES);

    // 4. layer1 sparse attention + ELU -> x2 [4096, 512]
    att_kernel<true, true><<<dim3(NNODES, 8), 64>>>(h1, s1a, s2a, cnt, idxp, x2);

    // 5. layer2 GEMM: h2 = x2 @ W_out
    gemm_n64<<<dim3(64, 1, 1), 256>>>(x2, W_out, h2, NNODES, 512, 0, 0);

    // 6. layer2 scores
    scores<<<NNODES / 256, 256>>>(h2, a_out, s1b, s2b, NNODES);

    // 7. layer2 sparse attention -> out
    att_kernel<false, false><<<dim3(NNODES, 1), 64>>>(h2, s1b, s2b, cnt, idxp, out);
}

// round 2
// speedup vs baseline: 1.3607x; 1.3607x over previous
#include <cuda_runtime.h>
#include <cuda_bf16.h>
#include <math.h>

#define NNODES 4096
#define MAXDEG 256
#define ALPHA  0.2f
#define NN64   ((size_t)NNODES * 64)

// ---------------- scratch (no allocations allowed) ----------------
__device__ int   g_cnt[NNODES];
__device__ int   g_idx[NNODES * MAXDEG];
__device__ float g_h1 [8 * NNODES * 64];   // layer1 per-head features [hd][n][64]
__device__ float g_s1a[8 * NNODES];
__device__ float g_s2a[8 * NNODES];
__device__ float g_x2 [NNODES * 512];      // elu(hp) reshaped [n][hd*64+d]
__device__ float g_h2p[4 * NNODES * 64];   // layer2 split-K partials
__device__ float g_h2 [NNODES * 64];
__device__ float g_s1b[NNODES];
__device__ float g_s2b[NNODES];

__device__ __forceinline__ float lrelu(float x) { return x > 0.f ? x : ALPHA * x; }

// ---------------- CSR build: one block per row ----------------
__global__ void build_csr(const float* __restrict__ adj, int* __restrict__ cnt,
                          int* __restrict__ idx) {
    int row = blockIdx.x;
    __shared__ int s_idx[MAXDEG];
    __shared__ int s_cnt;
    if (threadIdx.x == 0) s_cnt = 0;
    __syncthreads();
    const float4* r = (const float4*)(adj + (size_t)row * NNODES);
    for (int c = threadIdx.x; c < NNODES / 4; c += blockDim.x) {
        float4 v = r[c];
        if (v.x > 0.f) { int p = atomicAdd(&s_cnt, 1); if (p < MAXDEG) s_idx[p] = c * 4 + 0; }
        if (v.y > 0.f) { int p = atomicAdd(&s_cnt, 1); if (p < MAXDEG) s_idx[p] = c * 4 + 1; }
        if (v.z > 0.f) { int p = atomicAdd(&s_cnt, 1); if (p < MAXDEG) s_idx[p] = c * 4 + 2; }
        if (v.w > 0.f) { int p = atomicAdd(&s_cnt, 1); if (p < MAXDEG) s_idx[p] = c * 4 + 3; }
    }
    __syncthreads();
    int n = min(s_cnt, MAXDEG);
    if (threadIdx.x == 0) cnt[row] = n;
    for (int i = threadIdx.x; i < n; i += blockDim.x) idx[row * MAXDEG + i] = s_idx[i];
}

// ---------------- layer1 GEMM (128x64 tile, 8x4 micro) + fused scores ----------
// C[hd] = A @ B[hd]; A:[4096,K] row-major, B:[K,64]. Also s1/s2 = C . a1/a2.
__global__ void gemm_fused(const float* __restrict__ A, const float* __restrict__ B,
                           float* __restrict__ C, int K,
                           const float* __restrict__ a,
                           float* __restrict__ s1, float* __restrict__ s2) {
    __shared__ float As[16][132];
    __shared__ float Bs[16][64];
    int m0 = blockIdx.x * 128;
    int hd = blockIdx.z;
    const float* Bb = B + (size_t)hd * K * 64;
    float*       Cb = C + (size_t)hd * NN64;
    int tid = threadIdx.x;
    int tx = tid & 15, ty = tid >> 4;
    int kkA = tid & 15, mmA = tid >> 4;
    int kkB = tid >> 4, nnB = (tid & 15) * 4;
    float c[8][4] = {};

    for (int k0 = 0; k0 < K; k0 += 16) {
        #pragma unroll
        for (int p = 0; p < 8; p++)
            As[kkA][mmA + p * 16] = A[(size_t)(m0 + mmA + p * 16) * K + k0 + kkA];
        *(float4*)&Bs[kkB][nnB] = *(const float4*)&Bb[(size_t)(k0 + kkB) * 64 + nnB];
        __syncthreads();
        #pragma unroll
        for (int k = 0; k < 16; k++) {
            float4 b4 = *(const float4*)&Bs[k][tx * 4];
            float ar[8];
            #pragma unroll
            for (int i = 0; i < 8; i++) ar[i] = As[k][ty * 8 + i];
            #pragma unroll
            for (int i = 0; i < 8; i++) {
                c[i][0] += ar[i] * b4.x; c[i][1] += ar[i] * b4.y;
                c[i][2] += ar[i] * b4.z; c[i][3] += ar[i] * b4.w;
            }
        }
        __syncthreads();
    }

    const float* a1 = a + hd * 128;
    float a1r[4], a2r[4];
    #pragma unroll
    for (int j = 0; j < 4; j++) { a1r[j] = a1[tx * 4 + j]; a2r[j] = a1[64 + tx * 4 + j]; }
    #pragma unroll
    for (int i = 0; i < 8; i++) {
        int r = m0 + ty * 8 + i;
        float4 v = make_float4(c[i][0], c[i][1], c[i][2], c[i][3]);
        *(float4*)&Cb[(size_t)r * 64 + tx * 4] = v;
        float p1 = v.x * a1r[0] + v.y * a1r[1] + v.z * a1r[2] + v.w * a1r[3];
        float p2 = v.x * a2r[0] + v.y * a2r[1] + v.z * a2r[2] + v.w * a2r[3];
        #pragma unroll
        for (int o = 8; o > 0; o >>= 1) {
            p1 += __shfl_xor_sync(0xffffffffu, p1, o);
            p2 += __shfl_xor_sync(0xffffffffu, p2, o);
        }
        if (tx == 0) {
            s1[(size_t)hd * NNODES + r] = p1;
            s2[(size_t)hd * NNODES + r] = p2;
        }
    }
}

// ---------------- layer2 GEMM split-K: 64x64 tile, 4x4 micro -------------------
// part[z] = A[:, z*128:(z+1)*128] @ B[z*128:(z+1)*128, :]
__global__ void gemm_splitk(const float* __restrict__ A, const float* __restrict__ B,
                            float* __restrict__ part) {
    __shared__ float As[16][68];
    __shared__ float Bs[16][68];
    int m0 = blockIdx.x * 64;
    int z  = blockIdx.z;
    int kbase = z * 128;
    float* Cb = part + (size_t)z * NN64;
    int tid = threadIdx.x;
    int tx = tid & 15, ty = tid >> 4;
    float c[4][4] = {};

    for (int k0 = kbase; k0 < kbase + 128; k0 += 16) {
        #pragma unroll
        for (int p = 0; p < 4; p++) {
            int mm = (tid >> 4) + p * 16;
            int kk = tid & 15;
            As[kk][mm] = A[(size_t)(m0 + mm) * 512 + k0 + kk];
        }
        #pragma unroll
        for (int p = 0; p < 4; p++) {
            int kk = (tid >> 6) + p * 4;
            int nn = tid & 63;
            Bs[kk][nn] = B[(size_t)(k0 + kk) * 64 + nn];
        }
        __syncthreads();
        #pragma unroll
        for (int k = 0; k < 16; k++) {
            float4 a4 = *(const float4*)&As[k][ty * 4];
            float4 b4 = *(const float4*)&Bs[k][tx * 4];
            c[0][0] += a4.x * b4.x; c[0][1] += a4.x * b4.y; c[0][2] += a4.x * b4.z; c[0][3] += a4.x * b4.w;
            c[1][0] += a4.y * b4.x; c[1][1] += a4.y * b4.y; c[1][2] += a4.y * b4.z; c[1][3] += a4.y * b4.w;
            c[2][0] += a4.z * b4.x; c[2][1] += a4.z * b4.y; c[2][2] += a4.z * b4.z; c[2][3] += a4.z * b4.w;
            c[3][0] += a4.w * b4.x; c[3][1] += a4.w * b4.y; c[3][2] += a4.w * b4.z; c[3][3] += a4.w * b4.w;
        }
        __syncthreads();
    }
    #pragma unroll
    for (int i = 0; i < 4; i++) {
        float4 v = make_float4(c[i][0], c[i][1], c[i][2], c[i][3]);
        *(float4*)&Cb[(size_t)(m0 + ty * 4 + i) * 64 + tx * 4] = v;
    }
}

// ---------------- layer2 reduce partials + scores ------------------------------
__global__ void reduce_scores2(const float* __restrict__ part, const float* __restrict__ a,
                               float* __restrict__ h2, float* __restrict__ s1,
                               float* __restrict__ s2) {
    int row = blockIdx.x;
    int d = threadIdx.x;            // 64 threads
    size_t off = (size_t)row * 64 + d;
    float v = part[off] + part[off + NN64] + part[off + 2 * NN64] + part[off + 3 * NN64];
    h2[off] = v;
    float p1 = v * a[d];
    float p2 = v * a[64 + d];
    #pragma unroll
    for (int o = 16; o > 0; o >>= 1) {
        p1 += __shfl_xor_sync(0xffffffffu, p1, o);
        p2 += __shfl_xor_sync(0xffffffffu, p2, o);
    }
    __shared__ float r1[2], r2[2];
    if ((d & 31) == 0) { r1[d >> 5] = p1; r2[d >> 5] = p2; }
    __syncthreads();
    if (d == 0) { s1[row] = r1[0] + r1[1]; s2[row] = r2[0] + r2[1]; }
}

// ---------------- layer1 fused 8-head sparse attention -------------------------
// block = row, 512 threads: warp pair per head; lane handles 2 channels (float2)
__global__ void att1_kernel(const float* __restrict__ h, const float* __restrict__ s1,
                            const float* __restrict__ s2, const int* __restrict__ cnt,
                            const int* __restrict__ idx, float* __restrict__ out) {
    int row  = blockIdx.x;
    int tid  = threadIdx.x;
    int warp = tid >> 5;
    int lane = tid & 31;
    int head = warp >> 1;
    int sub  = warp & 1;
    int t64  = sub * 32 + lane;

    __shared__ int    s_nbr[MAXDEG];
    __shared__ float  s_w[8][MAXDEG];
    __shared__ float  s_red[8][2];
    __shared__ float  s_z[8][2];
    __shared__ float2 s_acc[8][32];

    int n = cnt[row];
    const int* ip = idx + row * MAXDEG;
    for (int i = tid; i < n; i += 512) s_nbr[i] = ip[i];
    __syncthreads();

    const float* s2h = s2 + (size_t)head * NNODES;
    float s1i = s1[(size_t)head * NNODES + row];

    // row max (lrelu monotone)
    float mx = -3.0e38f;
    for (int i = t64; i < n; i += 64) mx = fmaxf(mx, s2h[s_nbr[i]]);
    #pragma unroll
    for (int o = 16; o > 0; o >>= 1) mx = fmaxf(mx, __shfl_xor_sync(0xffffffffu, mx, o));
    if (lane == 0) s_red[head][sub] = mx;
    __syncthreads();
    mx = fmaxf(s_red[head][0], s_red[head][1]);
    float m = lrelu(s1i + mx);

    // weights + Z
    float zp = 0.f;
    for (int i = t64; i < n; i += 64) {
        float e = lrelu(s1i + s2h[s_nbr[i]]);
        float w = __expf(e - m);
        s_w[head][i] = w;
        zp += w;
    }
    #pragma unroll
    for (int o = 16; o > 0; o >>= 1) zp += __shfl_xor_sync(0xffffffffu, zp, o);
    if (lane == 0) s_z[head][sub] = zp;
    __syncthreads();
    float Z = s_z[head][0] + s_z[head][1];

    // gather: warp 'sub' takes neighbors of matching parity, lane -> 2 channels
    const float2* hh = (const float2*)(h + (size_t)head * NN64);
    float2 acc = make_float2(0.f, 0.f);
    int i = sub;
    for (; i + 6 < n; i += 8) {
        float w0 = s_w[head][i],     w1 = s_w[head][i + 2];
        float w2 = s_w[head][i + 4], w3 = s_w[head][i + 6];
        float2 v0 = hh[(size_t)s_nbr[i]     * 32 + lane];
        float2 v1 = hh[(size_t)s_nbr[i + 2] * 32 + lane];
        float2 v2 = hh[(size_t)s_nbr[i + 4] * 32 + lane];
        float2 v3 = hh[(size_t)s_nbr[i + 6] * 32 + lane];
        acc.x += w0 * v0.x; acc.y += w0 * v0.y;
        acc.x += w1 * v1.x; acc.y += w1 * v1.y;
        acc.x += w2 * v2.x; acc.y += w2 * v2.y;
        acc.x += w3 * v3.x; acc.y += w3 * v3.y;
    }
    for (; i < n; i += 2) {
        float w = s_w[head][i];
        float2 v = hh[(size_t)s_nbr[i] * 32 + lane];
        acc.x += w * v.x; acc.y += w * v.y;
    }
    if (sub == 1) s_acc[head][lane] = acc;
    __syncthreads();
    if (sub == 0) {
        float2 o2 = s_acc[head][lane];
        float inv = 1.f / Z;
        float ox = (acc.x + o2.x) * inv;
        float oy = (acc.y + o2.y) * inv;
        ox = ox > 0.f ? ox : expm1f(ox);
        oy = oy > 0.f ? oy : expm1f(oy);
        ((float2*)out)[(size_t)row * 256 + head * 32 + lane] = make_float2(ox, oy);
    }
}

// ---------------- layer2 sparse attention (single head) ------------------------
__global__ void att2_kernel(const float* __restrict__ h, const float* __restrict__ s1,
                            const float* __restrict__ s2, const int* __restrict__ cnt,
                            const int* __restrict__ idx, float* __restrict__ out) {
    int row = blockIdx.x;
    int tid = threadIdx.x;   // 64

    __shared__ int   s_nbr[MAXDEG];
    __shared__ float s_w[MAXDEG];
    __shared__ float s_red[2];

    int n = cnt[row];
    const int* ip = idx + row * MAXDEG;
    for (int i = tid; i < n; i += 64) s_nbr[i] = ip[i];
    __syncthreads();

    float s1i = s1[row];

    float mx = -3.0e38f;
    for (int i = tid; i < n; i += 64) mx = fmaxf(mx, s2[s_nbr[i]]);
    #pragma unroll
    for (int o = 16; o > 0; o >>= 1) mx = fmaxf(mx, __shfl_xor_sync(0xffffffffu, mx, o));
    if ((tid & 31) == 0) s_red[tid >> 5] = mx;
    __syncthreads();
    mx = fmaxf(s_red[0], s_red[1]);
    float m = lrelu(s1i + mx);
    __syncthreads();

    float zp = 0.f;
    for (int i = tid; i < n; i += 64) {
        float e = lrelu(s1i + s2[s_nbr[i]]);
        float w = __expf(e - m);
        s_w[i] = w;
        zp += w;
    }
    #pragma unroll
    for (int o = 16; o > 0; o >>= 1) zp += __shfl_xor_sync(0xffffffffu, zp, o);
    if ((tid & 31) == 0) s_red[tid >> 5] = zp;
    __syncthreads();
    float Z = s_red[0] + s_red[1];

    float acc = 0.f;
    int i = 0;
    for (; i + 4 <= n; i += 4) {
        float v0 = h[(size_t)s_nbr[i + 0] * 64 + tid];
        float v1 = h[(size_t)s_nbr[i + 1] * 64 + tid];
        float v2 = h[(size_t)s_nbr[i + 2] * 64 + tid];
        float v3 = h[(size_t)s_nbr[i + 3] * 64 + tid];
        acc += s_w[i + 0] * v0 + s_w[i + 1] * v1 + s_w[i + 2] * v2 + s_w[i + 3] * v3;
    }
    for (; i < n; i++) acc += s_w[i] * h[(size_t)s_nbr[i] * 64 + tid];

    out[(size_t)row * 64 + tid] = acc / Z;
}

// ---------------- launcher ----------------
extern "C" void kernel_launch(void* const* d_in, const int* in_sizes, int n_in,
                              void* d_out, int out_size) {
    const float* features = (const float*)d_in[0];   // [4096, 256]
    const float* adj      = (const float*)d_in[1];   // [4096, 4096]
    const float* W_heads  = (const float*)d_in[2];   // [8, 256, 64]
    const float* a_heads  = (const float*)d_in[3];   // [8, 128, 1]
    const float* W_out    = (const float*)d_in[4];   // [512, 64]
    const float* a_out    = (const float*)d_in[5];   // [128, 1]
    float* out = (float*)d_out;                      // [4096, 64]

    int   *cnt, *idxp;
    float *h1, *s1a, *s2a, *x2, *h2p, *h2, *s1b, *s2b;
    cudaGetSymbolAddress((void**)&cnt,  g_cnt);
    cudaGetSymbolAddress((void**)&idxp, g_idx);
    cudaGetSymbolAddress((void**)&h1,   g_h1);
    cudaGetSymbolAddress((void**)&s1a,  g_s1a);
    cudaGetSymbolAddress((void**)&s2a,  g_s2a);
    cudaGetSymbolAddress((void**)&x2,   g_x2);
    cudaGetSymbolAddress((void**)&h2p,  g_h2p);
    cudaGetSymbolAddress((void**)&h2,   g_h2);
    cudaGetSymbolAddress((void**)&s1b,  g_s1b);
    cudaGetSymbolAddress((void**)&s2b,  g_s2b);

    // 1. adjacency -> CSR
    build_csr<<<NNODES, 256>>>(adj, cnt, idxp);

    // 2. layer1 GEMM + scores: h1[hd] = features @ W_heads[hd], s1a/s2a fused
    gemm_fused<<<dim3(32, 1, 8), 256>>>(features, W_heads, h1, 256, a_heads, s1a, s2a);

    // 3. layer1 8-head sparse attention + ELU -> x2 [4096, 512]
    att1_kernel<<<NNODES, 512>>>(h1, s1a, s2a, cnt, idxp, x2);

    // 4. layer2 GEMM split-K partials
    gemm_splitk<<<dim3(64, 1, 4), 256>>>(x2, W_out, h2p);

    // 5. reduce partials + layer2 scores
    reduce_scores2<<<NNODES, 64>>>(h2p, a_out, h2, s1b, s2b);

    // 6. layer2 sparse attention -> out
    att2_kernel<<<NNODES, 64>>>(h2, s1b, s2b, cnt, idxp, out);
}

// round 3
// speedup vs baseline: 1.3942x; 1.0247x over previous
#include <cuda_runtime.h>
#include <cuda_fp16.h>
#include <math.h>

#define NNODES 4096
#define MAXDEG 256
#define ALPHA  0.2f
#define NN64   ((size_t)NNODES * 64)

// ---------------- scratch (no allocations allowed) ----------------
__device__ int    g_cnt[NNODES];
__device__ int    g_idx[NNODES * MAXDEG];
__device__ __half g_h1h[8 * NNODES * 64];   // layer1 features, fp16 gather table
__device__ float  g_s1a[8 * NNODES];
__device__ float  g_s2a[8 * NNODES];
__device__ float  g_x2 [NNODES * 512];      // elu(hp) fp32 (GEMM2 input)
__device__ float  g_h2p[8 * NNODES * 64];   // layer2 split-K partials
__device__ __half g_h2h[NNODES * 64];       // layer2 features, fp16 gather table
__device__ float  g_s1b[NNODES];
__device__ float  g_s2b[NNODES];

__device__ __forceinline__ float lrelu(float x) { return x > 0.f ? x : ALPHA * x; }

// ---------------- CSR build: one block per row ----------------
__global__ void build_csr(const float* __restrict__ adj, int* __restrict__ cnt,
                          int* __restrict__ idx) {
    int row = blockIdx.x;
    __shared__ int s_idx[MAXDEG];
    __shared__ int s_cnt;
    if (threadIdx.x == 0) s_cnt = 0;
    __syncthreads();
    const float4* r = (const float4*)(adj + (size_t)row * NNODES);
    for (int c = threadIdx.x; c < NNODES / 4; c += blockDim.x) {
        float4 v = r[c];
        if (v.x > 0.f) { int p = atomicAdd(&s_cnt, 1); if (p < MAXDEG) s_idx[p] = c * 4 + 0; }
        if (v.y > 0.f) { int p = atomicAdd(&s_cnt, 1); if (p < MAXDEG) s_idx[p] = c * 4 + 1; }
        if (v.z > 0.f) { int p = atomicAdd(&s_cnt, 1); if (p < MAXDEG) s_idx[p] = c * 4 + 2; }
        if (v.w > 0.f) { int p = atomicAdd(&s_cnt, 1); if (p < MAXDEG) s_idx[p] = c * 4 + 3; }
    }
    __syncthreads();
    int n = min(s_cnt, MAXDEG);
    if (threadIdx.x == 0) cnt[row] = n;
    for (int i = threadIdx.x; i < n; i += blockDim.x) idx[row * MAXDEG + i] = s_idx[i];
}

// ---------------- layer1 GEMM (128x64 tile, 8x4 micro) + fused scores + fp16 out
__global__ void gemm_fused(const float* __restrict__ A, const float* __restrict__ B,
                           __half* __restrict__ Ch, int K,
                           const float* __restrict__ a,
                           float* __restrict__ s1, float* __restrict__ s2) {
    __shared__ __align__(16) float As[16][132];
    __shared__ __align__(16) float Bs[16][64];
    int m0 = blockIdx.x * 128;
    int hd = blockIdx.z;
    const float* Bb = B + (size_t)hd * K * 64;
    int tid = threadIdx.x;
    int tx = tid & 15, ty = tid >> 4;
    int kkA = tid & 15, mmA = tid >> 4;
    int kkB = tid >> 4, nnB = (tid & 15) * 4;
    float c[8][4] = {};

    for (int k0 = 0; k0 < K; k0 += 16) {
        #pragma unroll
        for (int p = 0; p < 8; p++)
            As[kkA][mmA + p * 16] = A[(size_t)(m0 + mmA + p * 16) * K + k0 + kkA];
        *(float4*)&Bs[kkB][nnB] = *(const float4*)&Bb[(size_t)(k0 + kkB) * 64 + nnB];
        __syncthreads();
        #pragma unroll
        for (int k = 0; k < 16; k++) {
            float4 b4 = *(const float4*)&Bs[k][tx * 4];
            float4 a0 = *(const float4*)&As[k][ty * 8];
            float4 a1 = *(const float4*)&As[k][ty * 8 + 4];
            float ar[8] = {a0.x, a0.y, a0.z, a0.w, a1.x, a1.y, a1.z, a1.w};
            #pragma unroll
            for (int i = 0; i < 8; i++) {
                c[i][0] += ar[i] * b4.x; c[i][1] += ar[i] * b4.y;
                c[i][2] += ar[i] * b4.z; c[i][3] += ar[i] * b4.w;
            }
        }
        __syncthreads();
    }

    const float* a1p = a + hd * 128;
    float a1r[4], a2r[4];
    #pragma unroll
    for (int j = 0; j < 4; j++) { a1r[j] = a1p[tx * 4 + j]; a2r[j] = a1p[64 + tx * 4 + j]; }
    #pragma unroll
    for (int i = 0; i < 8; i++) {
        int r = m0 + ty * 8 + i;
        float4 v = make_float4(c[i][0], c[i][1], c[i][2], c[i][3]);
        __half2* hp = (__half2*)(Ch + (size_t)hd * NN64 + (size_t)r * 64 + tx * 4);
        hp[0] = __floats2half2_rn(v.x, v.y);
        hp[1] = __floats2half2_rn(v.z, v.w);
        float p1 = v.x * a1r[0] + v.y * a1r[1] + v.z * a1r[2] + v.w * a1r[3];
        float p2 = v.x * a2r[0] + v.y * a2r[1] + v.z * a2r[2] + v.w * a2r[3];
        #pragma unroll
        for (int o = 8; o > 0; o >>= 1) {
            p1 += __shfl_xor_sync(0xffffffffu, p1, o);
            p2 += __shfl_xor_sync(0xffffffffu, p2, o);
        }
        if (tx == 0) {
            s1[(size_t)hd * NNODES + r] = p1;
            s2[(size_t)hd * NNODES + r] = p2;
        }
    }
}

// ---------------- layer1 attention: block=row, warp=head, fp16 gather ----------
__global__ void att1_kernel(const __half2* __restrict__ hh, const float* __restrict__ s1,
                            const float* __restrict__ s2, const int* __restrict__ cnt,
                            const int* __restrict__ idx, float* __restrict__ out) {
    int row  = blockIdx.x;
    int tid  = threadIdx.x;       // 256
    int head = tid >> 5;
    int lane = tid & 31;

    __shared__ int   s_nbr[MAXDEG];
    __shared__ float s_w[8][MAXDEG];

    int n = cnt[row];
    const int* ip = idx + row * MAXDEG;
    for (int i = tid; i < n; i += 256) s_nbr[i] = ip[i];
    __syncthreads();

    const float* s2h = s2 + (size_t)head * NNODES;
    float s1i = s1[(size_t)head * NNODES + row];

    // row max (lrelu monotone)
    float mx = -3.0e38f;
    for (int i = lane; i < n; i += 32) mx = fmaxf(mx, s2h[s_nbr[i]]);
    #pragma unroll
    for (int o = 16; o > 0; o >>= 1) mx = fmaxf(mx, __shfl_xor_sync(0xffffffffu, mx, o));
    float m = lrelu(s1i + mx);

    // weights + Z
    float zp = 0.f;
    for (int i = lane; i < n; i += 32) {
        float e = lrelu(s1i + s2h[s_nbr[i]]);
        float w = __expf(e - m);
        s_w[head][i] = w;
        zp += w;
    }
    #pragma unroll
    for (int o = 16; o > 0; o >>= 1) zp += __shfl_xor_sync(0xffffffffu, zp, o);
    __syncwarp();

    // gather fp16 rows: lane covers 2 channels (half2)
    const __half2* hb = hh + (size_t)head * NNODES * 32;
    float2 acc = make_float2(0.f, 0.f);
    int i = 0;
    for (; i + 3 < n; i += 4) {
        float w0 = s_w[head][i],     w1 = s_w[head][i + 1];
        float w2 = s_w[head][i + 2], w3 = s_w[head][i + 3];
        float2 v0 = __half22float2(hb[(size_t)s_nbr[i]     * 32 + lane]);
        float2 v1 = __half22float2(hb[(size_t)s_nbr[i + 1] * 32 + lane]);
        float2 v2 = __half22float2(hb[(size_t)s_nbr[i + 2] * 32 + lane]);
        float2 v3 = __half22float2(hb[(size_t)s_nbr[i + 3] * 32 + lane]);
        acc.x += w0 * v0.x; acc.y += w0 * v0.y;
        acc.x += w1 * v1.x; acc.y += w1 * v1.y;
        acc.x += w2 * v2.x; acc.y += w2 * v2.y;
        acc.x += w3 * v3.x; acc.y += w3 * v3.y;
    }
    for (; i < n; i++) {
        float w = s_w[head][i];
        float2 v = __half22float2(hb[(size_t)s_nbr[i] * 32 + lane]);
        acc.x += w * v.x; acc.y += w * v.y;
    }

    float inv = 1.f / zp;
    float ox = acc.x * inv, oy = acc.y * inv;
    ox = ox > 0.f ? ox : expm1f(ox);
    oy = oy > 0.f ? oy : expm1f(oy);
    ((float2*)out)[(size_t)row * 256 + head * 32 + lane] = make_float2(ox, oy);
}

// ---------------- layer2 GEMM split-K(8): 64x64 tile, 4x4 micro ----------------
__global__ void gemm_splitk(const float* __restrict__ A, const float* __restrict__ B,
                            float* __restrict__ part) {
    __shared__ __align__(16) float As[16][68];
    __shared__ __align__(16) float Bs[16][68];
    int m0 = blockIdx.x * 64;
    int z  = blockIdx.z;
    int kbase = z * 64;
    float* Cb = part + (size_t)z * NN64;
    int tid = threadIdx.x;
    int tx = tid & 15, ty = tid >> 4;
    float c[4][4] = {};

    for (int k0 = kbase; k0 < kbase + 64; k0 += 16) {
        #pragma unroll
        for (int p = 0; p < 4; p++) {
            int mm = (tid >> 4) + p * 16;
            int kk = tid & 15;
            As[kk][mm] = A[(size_t)(m0 + mm) * 512 + k0 + kk];
        }
        #pragma unroll
        for (int p = 0; p < 4; p++) {
            int kk = (tid >> 6) + p * 4;
            int nn = tid & 63;
            Bs[kk][nn] = B[(size_t)(k0 + kk) * 64 + nn];
        }
        __syncthreads();
        #pragma unroll
        for (int k = 0; k < 16; k++) {
            float4 a4 = *(const float4*)&As[k][ty * 4];
            float4 b4 = *(const float4*)&Bs[k][tx * 4];
            c[0][0] += a4.x * b4.x; c[0][1] += a4.x * b4.y; c[0][2] += a4.x * b4.z; c[0][3] += a4.x * b4.w;
            c[1][0] += a4.y * b4.x; c[1][1] += a4.y * b4.y; c[1][2] += a4.y * b4.z; c[1][3] += a4.y * b4.w;
            c[2][0] += a4.z * b4.x; c[2][1] += a4.z * b4.y; c[2][2] += a4.z * b4.z; c[2][3] += a4.z * b4.w;
            c[3][0] += a4.w * b4.x; c[3][1] += a4.w * b4.y; c[3][2] += a4.w * b4.z; c[3][3] += a4.w * b4.w;
        }
        __syncthreads();
    }
    #pragma unroll
    for (int i = 0; i < 4; i++) {
        float4 v = make_float4(c[i][0], c[i][1], c[i][2], c[i][3]);
        *(float4*)&Cb[(size_t)(m0 + ty * 4 + i) * 64 + tx * 4] = v;
    }
}

// ---------------- layer2 reduce partials + scores + fp16 table -----------------
__global__ void reduce_scores2(const float* __restrict__ part, const float* __restrict__ a,
                               __half* __restrict__ h2h, float* __restrict__ s1,
                               float* __restrict__ s2) {
    int row = blockIdx.x;
    int d = threadIdx.x;            // 64 threads
    size_t off = (size_t)row * 64 + d;
    float v = 0.f;
    #pragma unroll
    for (int z = 0; z < 8; z++) v += part[off + (size_t)z * NN64];
    h2h[off] = __float2half_rn(v);
    float p1 = v * a[d];
    float p2 = v * a[64 + d];
    #pragma unroll
    for (int o = 16; o > 0; o >>= 1) {
        p1 += __shfl_xor_sync(0xffffffffu, p1, o);
        p2 += __shfl_xor_sync(0xffffffffu, p2, o);
    }
    __shared__ float r1[2], r2[2];
    if ((d & 31) == 0) { r1[d >> 5] = p1; r2[d >> 5] = p2; }
    __syncthreads();
    if (d == 0) { s1[row] = r1[0] + r1[1]; s2[row] = r2[0] + r2[1]; }
}

// ---------------- layer2 attention: warp per row, fp16 gather ------------------
__global__ void att2_kernel(const __half2* __restrict__ hh, const float* __restrict__ s1,
                            const float* __restrict__ s2, const int* __restrict__ cnt,
                            const int* __restrict__ idx, float* __restrict__ out) {
    int wr   = threadIdx.x >> 5;     // 8 warps
    int lane = threadIdx.x & 31;
    int row  = blockIdx.x * 8 + wr;

    __shared__ int   s_nbr[8][MAXDEG];
    __shared__ float s_w[8][MAXDEG];

    int n = cnt[row];
    const int* ip = idx + row * MAXDEG;
    for (int i = lane; i < n; i += 32) s_nbr[wr][i] = ip[i];
    __syncwarp();

    float s1i = s1[row];

    float mx = -3.0e38f;
    for (int i = lane; i < n; i += 32) mx = fmaxf(mx, s2[s_nbr[wr][i]]);
    #pragma unroll
    for (int o = 16; o > 0; o >>= 1) mx = fmaxf(mx, __shfl_xor_sync(0xffffffffu, mx, o));
    float m = lrelu(s1i + mx);

    float zp = 0.f;
    for (int i = lane; i < n; i += 32) {
        float e = lrelu(s1i + s2[s_nbr[wr][i]]);
        float w = __expf(e - m);
        s_w[wr][i] = w;
        zp += w;
    }
    #pragma unroll
    for (int o = 16; o > 0; o >>= 1) zp += __shfl_xor_sync(0xffffffffu, zp, o);
    __syncwarp();

    float2 acc = make_float2(0.f, 0.f);
    int i = 0;
    for (; i + 3 < n; i += 4) {
        float w0 = s_w[wr][i],     w1 = s_w[wr][i + 1];
        float w2 = s_w[wr][i + 2], w3 = s_w[wr][i + 3];
        float2 v0 = __half22float2(hh[(size_t)s_nbr[wr][i]     * 32 + lane]);
        float2 v1 = __half22float2(hh[(size_t)s_nbr[wr][i + 1] * 32 + lane]);
        float2 v2 = __half22float2(hh[(size_t)s_nbr[wr][i + 2] * 32 + lane]);
        float2 v3 = __half22float2(hh[(size_t)s_nbr[wr][i + 3] * 32 + lane]);
        acc.x += w0 * v0.x; acc.y += w0 * v0.y;
        acc.x += w1 * v1.x; acc.y += w1 * v1.y;
        acc.x += w2 * v2.x; acc.y += w2 * v2.y;
        acc.x += w3 * v3.x; acc.y += w3 * v3.y;
    }
    for (; i < n; i++) {
        float w = s_w[wr][i];
        float2 v = __half22float2(hh[(size_t)s_nbr[wr][i] * 32 + lane]);
        acc.x += w * v.x; acc.y += w * v.y;
    }
    float inv = 1.f / zp;
    ((float2*)out)[(size_t)row * 32 + lane] = make_float2(acc.x * inv, acc.y * inv);
}

// ---------------- launcher ----------------
extern "C" void kernel_launch(void* const* d_in, const int* in_sizes, int n_in,
                              void* d_out, int out_size) {
    const float* features = (const float*)d_in[0];   // [4096, 256]
    const float* adj      = (const float*)d_in[1];   // [4096, 4096]
    const float* W_heads  = (const float*)d_in[2];   // [8, 256, 64]
    const float* a_heads  = (const float*)d_in[3];   // [8, 128, 1]
    const float* W_out    = (const float*)d_in[4];   // [512, 64]
    const float* a_out    = (const float*)d_in[5];   // [128, 1]
    float* out = (float*)d_out;                      // [4096, 64]

    int    *cnt, *idxp;
    float  *s1a, *s2a, *x2, *h2p, *s1b, *s2b;
    __half *h1h, *h2h;
    cudaGetSymbolAddress((void**)&cnt,  g_cnt);
    cudaGetSymbolAddress((void**)&idxp, g_idx);
    cudaGetSymbolAddress((void**)&h1h,  g_h1h);
    cudaGetSymbolAddress((void**)&s1a,  g_s1a);
    cudaGetSymbolAddress((void**)&s2a,  g_s2a);
    cudaGetSymbolAddress((void**)&x2,   g_x2);
    cudaGetSymbolAddress((void**)&h2p,  g_h2p);
    cudaGetSymbolAddress((void**)&h2h,  g_h2h);
    cudaGetSymbolAddress((void**)&s1b,  g_s1b);
    cudaGetSymbolAddress((void**)&s2b,  g_s2b);

    // fork: build_csr (HBM-bound) runs concurrently with gemm_fused (FMA-bound)
    cudaStream_t sB;
    cudaStreamCreateWithFlags(&sB, cudaStreamNonBlocking);
    cudaEvent_t eF, eJ;
    cudaEventCreateWithFlags(&eF, cudaEventDisableTiming);
    cudaEventCreateWithFlags(&eJ, cudaEventDisableTiming);

    cudaEventRecord(eF, 0);
    cudaStreamWaitEvent(sB, eF, 0);
    build_csr<<<NNODES, 256, 0, sB>>>(adj, cnt, idxp);
    cudaEventRecord(eJ, sB);

    gemm_fused<<<dim3(32, 1, 8), 256>>>(features, W_heads, h1h, 256, a_heads, s1a, s2a);

    cudaStreamWaitEvent(0, eJ, 0);   // join before att1

    att1_kernel<<<NNODES, 256>>>((const __half2*)h1h, s1a, s2a, cnt, idxp, x2);
    gemm_splitk<<<dim3(64, 1, 8), 256>>>(x2, W_out, h2p);
    reduce_scores2<<<NNODES, 64>>>(h2p, a_out, h2h, s1b, s2b);
    att2_kernel<<<NNODES / 8, 256>>>((const __half2*)h2h, s1b, s2b, cnt, idxp, out);
}

// round 4
// speedup vs baseline: 1.4561x; 1.0444x over previous
#include <cuda_runtime.h>
#include <cuda_fp16.h>
#include <math.h>

#define NNODES 4096
#define MAXDEG 256
#define ALPHA  0.2f
#define NN64   ((size_t)NNODES * 64)

// ---------------- scratch (no allocations allowed) ----------------
__device__ int    g_cnt[NNODES];
__device__ int    g_idx[NNODES * MAXDEG];
__device__ __half g_h1h[8 * NNODES * 64];   // layer1 features, fp16 gather table
__device__ float  g_s1a[8 * NNODES];
__device__ float  g_s2a[8 * NNODES];
__device__ float  g_x2 [NNODES * 512];      // elu(hp) fp32 (GEMM2 input)
__device__ float  g_h2p[8 * NNODES * 64];   // layer2 split-K partials
__device__ __half g_h2h[NNODES * 64];       // layer2 features, fp16 gather table
__device__ float  g_s1b[NNODES];
__device__ float  g_s2b[NNODES];

__device__ __forceinline__ float lrelu(float x) { return x > 0.f ? x : ALPHA * x; }
__device__ __forceinline__ void grid_dep_wait() {
    asm volatile("griddepcontrol.wait;" ::: "memory");
}

// ---------------- CSR build: one block per row ----------------
__global__ void build_csr(const float* __restrict__ adj, int* __restrict__ cnt,
                          int* __restrict__ idx) {
    int row = blockIdx.x;
    __shared__ int s_idx[MAXDEG];
    __shared__ int s_cnt;
    if (threadIdx.x == 0) s_cnt = 0;
    __syncthreads();
    const float4* r = (const float4*)(adj + (size_t)row * NNODES);
    for (int c = threadIdx.x; c < NNODES / 4; c += blockDim.x) {
        float4 v = r[c];
        if (v.x > 0.f) { int p = atomicAdd(&s_cnt, 1); if (p < MAXDEG) s_idx[p] = c * 4 + 0; }
        if (v.y > 0.f) { int p = atomicAdd(&s_cnt, 1); if (p < MAXDEG) s_idx[p] = c * 4 + 1; }
        if (v.z > 0.f) { int p = atomicAdd(&s_cnt, 1); if (p < MAXDEG) s_idx[p] = c * 4 + 2; }
        if (v.w > 0.f) { int p = atomicAdd(&s_cnt, 1); if (p < MAXDEG) s_idx[p] = c * 4 + 3; }
    }
    __syncthreads();
    int n = min(s_cnt, MAXDEG);
    if (threadIdx.x == 0) cnt[row] = n;
    for (int i = threadIdx.x; i < n; i += blockDim.x) idx[row * MAXDEG + i] = s_idx[i];
}

// ------- layer1 GEMM: 128x64 tile, 8x4 micro, double-buffered, fused scores ----
__global__ __launch_bounds__(256)
void gemm_fused(const float* __restrict__ A, const float* __restrict__ B,
                __half* __restrict__ Ch, const float* __restrict__ a,
                float* __restrict__ s1, float* __restrict__ s2) {
    const int K = 256;
    __shared__ __align__(16) float As[2][16][132];
    __shared__ __align__(16) float Bs[2][16][64];
    int m0 = blockIdx.x * 128;
    int hd = blockIdx.z;
    const float* Bb = B + (size_t)hd * K * 64;
    int tid = threadIdx.x;
    int tx = tid & 15, ty = tid >> 4;
    int aRow = tid >> 1;            // 0..127
    int aK0  = (tid & 1) * 8;       // 0 or 8
    int kkB  = tid >> 4;            // 0..15
    int nnB  = (tid & 15) * 4;

    float4 ra0, ra1, rb;
    const float* Ap = A + (size_t)(m0 + aRow) * K + aK0;
    ra0 = *(const float4*)(Ap + 0);
    ra1 = *(const float4*)(Ap + 4);
    rb  = *(const float4*)&Bb[(size_t)kkB * 64 + nnB];
    As[0][aK0 + 0][aRow] = ra0.x; As[0][aK0 + 1][aRow] = ra0.y;
    As[0][aK0 + 2][aRow] = ra0.z; As[0][aK0 + 3][aRow] = ra0.w;
    As[0][aK0 + 4][aRow] = ra1.x; As[0][aK0 + 5][aRow] = ra1.y;
    As[0][aK0 + 6][aRow] = ra1.z; As[0][aK0 + 7][aRow] = ra1.w;
    *(float4*)&Bs[0][kkB][nnB] = rb;
    __syncthreads();

    float c[8][4] = {};
    const int NT = K / 16;
    for (int t = 0; t < NT; t++) {
        int cur = t & 1, nxt = cur ^ 1;
        if (t + 1 < NT) {
            int k0 = (t + 1) * 16;
            ra0 = *(const float4*)(Ap + k0 + 0);
            ra1 = *(const float4*)(Ap + k0 + 4);
            rb  = *(const float4*)&Bb[(size_t)(k0 + kkB) * 64 + nnB];
        }
        #pragma unroll
        for (int k = 0; k < 16; k++) {
            float4 b4 = *(const float4*)&Bs[cur][k][tx * 4];
            float4 a0 = *(const float4*)&As[cur][k][ty * 8];
            float4 a1 = *(const float4*)&As[cur][k][ty * 8 + 4];
            float ar[8] = {a0.x, a0.y, a0.z, a0.w, a1.x, a1.y, a1.z, a1.w};
            #pragma unroll
            for (int i = 0; i < 8; i++) {
                c[i][0] += ar[i] * b4.x; c[i][1] += ar[i] * b4.y;
                c[i][2] += ar[i] * b4.z; c[i][3] += ar[i] * b4.w;
            }
        }
        if (t + 1 < NT) {
            As[nxt][aK0 + 0][aRow] = ra0.x; As[nxt][aK0 + 1][aRow] = ra0.y;
            As[nxt][aK0 + 2][aRow] = ra0.z; As[nxt][aK0 + 3][aRow] = ra0.w;
            As[nxt][aK0 + 4][aRow] = ra1.x; As[nxt][aK0 + 5][aRow] = ra1.y;
            As[nxt][aK0 + 6][aRow] = ra1.z; As[nxt][aK0 + 7][aRow] = ra1.w;
            *(float4*)&Bs[nxt][kkB][nnB] = rb;
        }
        __syncthreads();
    }

    const float* a1p = a + hd * 128;
    float a1r[4], a2r[4];
    #pragma unroll
    for (int j = 0; j < 4; j++) { a1r[j] = a1p[tx * 4 + j]; a2r[j] = a1p[64 + tx * 4 + j]; }
    #pragma unroll
    for (int i = 0; i < 8; i++) {
        int r = m0 + ty * 8 + i;
        float4 v = make_float4(c[i][0], c[i][1], c[i][2], c[i][3]);
        __half2* hp = (__half2*)(Ch + (size_t)hd * NN64 + (size_t)r * 64 + tx * 4);
        hp[0] = __floats2half2_rn(v.x, v.y);
        hp[1] = __floats2half2_rn(v.z, v.w);
        float p1 = v.x * a1r[0] + v.y * a1r[1] + v.z * a1r[2] + v.w * a1r[3];
        float p2 = v.x * a2r[0] + v.y * a2r[1] + v.z * a2r[2] + v.w * a2r[3];
        #pragma unroll
        for (int o = 8; o > 0; o >>= 1) {
            p1 += __shfl_xor_sync(0xffffffffu, p1, o);
            p2 += __shfl_xor_sync(0xffffffffu, p2, o);
        }
        if (tx == 0) {
            s1[(size_t)hd * NNODES + r] = p1;
            s2[(size_t)hd * NNODES + r] = p2;
        }
    }
}

// ---------------- layer1 attention: block=row, warp=head, fp16 gather ----------
__global__ void att1_kernel(const __half2* __restrict__ hh, const float* __restrict__ s1,
                            const float* __restrict__ s2, const int* __restrict__ cnt,
                            const int* __restrict__ idx, float* __restrict__ out) {
    int row  = blockIdx.x;
    int tid  = threadIdx.x;       // 256
    int head = tid >> 5;
    int lane = tid & 31;

    __shared__ int   s_nbr[MAXDEG];
    __shared__ float s_w[8][MAXDEG];

    int n = cnt[row];
    const int* ip = idx + row * MAXDEG;
    for (int i = tid; i < n; i += 256) s_nbr[i] = ip[i];
    __syncthreads();

    const float* s2h = s2 + (size_t)head * NNODES;
    float s1i = s1[(size_t)head * NNODES + row];

    float mx = -3.0e38f;
    for (int i = lane; i < n; i += 32) mx = fmaxf(mx, s2h[s_nbr[i]]);
    #pragma unroll
    for (int o = 16; o > 0; o >>= 1) mx = fmaxf(mx, __shfl_xor_sync(0xffffffffu, mx, o));
    float m = lrelu(s1i + mx);

    float zp = 0.f;
    for (int i = lane; i < n; i += 32) {
        float e = lrelu(s1i + s2h[s_nbr[i]]);
        float w = __expf(e - m);
        s_w[head][i] = w;
        zp += w;
    }
    #pragma unroll
    for (int o = 16; o > 0; o >>= 1) zp += __shfl_xor_sync(0xffffffffu, zp, o);
    __syncwarp();

    const __half2* hb = hh + (size_t)head * NNODES * 32;
    float2 acc = make_float2(0.f, 0.f);
    int i = 0;
    for (; i + 3 < n; i += 4) {
        float w0 = s_w[head][i],     w1 = s_w[head][i + 1];
        float w2 = s_w[head][i + 2], w3 = s_w[head][i + 3];
        float2 v0 = __half22float2(hb[(size_t)s_nbr[i]     * 32 + lane]);
        float2 v1 = __half22float2(hb[(size_t)s_nbr[i + 1] * 32 + lane]);
        float2 v2 = __half22float2(hb[(size_t)s_nbr[i + 2] * 32 + lane]);
        float2 v3 = __half22float2(hb[(size_t)s_nbr[i + 3] * 32 + lane]);
        acc.x += w0 * v0.x; acc.y += w0 * v0.y;
        acc.x += w1 * v1.x; acc.y += w1 * v1.y;
        acc.x += w2 * v2.x; acc.y += w2 * v2.y;
        acc.x += w3 * v3.x; acc.y += w3 * v3.y;
    }
    for (; i < n; i++) {
        float w = s_w[head][i];
        float2 v = __half22float2(hb[(size_t)s_nbr[i] * 32 + lane]);
        acc.x += w * v.x; acc.y += w * v.y;
    }

    float inv = 1.f / zp;
    float ox = acc.x * inv, oy = acc.y * inv;
    ox = ox > 0.f ? ox : expm1f(ox);
    oy = oy > 0.f ? oy : expm1f(oy);
    ((float2*)out)[(size_t)row * 256 + head * 32 + lane] = make_float2(ox, oy);
}

// ------- layer2 GEMM split-K(8): 64x64 tile, 8x4 micro, 128 thr, dbl-buffered --
__global__ __launch_bounds__(128)
void gemm_splitk(const float* __restrict__ A, const float* __restrict__ B,
                 float* __restrict__ part) {
    __shared__ __align__(16) float As[2][16][68];
    __shared__ __align__(16) float Bs[2][16][64];
    int m0 = blockIdx.x * 64;
    int z  = blockIdx.z;
    int kbase = z * 64;
    float* Cb = part + (size_t)z * NN64;
    int tid = threadIdx.x;
    int tx = tid & 15, ty = tid >> 4;     // ty 0..7
    int aRow = tid >> 1;                  // 0..63
    int aK0  = (tid & 1) * 8;
    int kkB0 = tid >> 4;                  // 0..7 (and +8)
    int nnB  = (tid & 15) * 4;

    grid_dep_wait();

    const float* Ap = A + (size_t)(m0 + aRow) * 512 + kbase + aK0;
    float4 ra0, ra1, rb0, rb1;
    ra0 = *(const float4*)(Ap + 0);
    ra1 = *(const float4*)(Ap + 4);
    rb0 = *(const float4*)&B[(size_t)(kbase + kkB0) * 64 + nnB];
    rb1 = *(const float4*)&B[(size_t)(kbase + kkB0 + 8) * 64 + nnB];
    As[0][aK0 + 0][aRow] = ra0.x; As[0][aK0 + 1][aRow] = ra0.y;
    As[0][aK0 + 2][aRow] = ra0.z; As[0][aK0 + 3][aRow] = ra0.w;
    As[0][aK0 + 4][aRow] = ra1.x; As[0][aK0 + 5][aRow] = ra1.y;
    As[0][aK0 + 6][aRow] = ra1.z; As[0][aK0 + 7][aRow] = ra1.w;
    *(float4*)&Bs[0][kkB0][nnB] = rb0;
    *(float4*)&Bs[0][kkB0 + 8][nnB] = rb1;
    __syncthreads();

    float c[8][4] = {};
    #pragma unroll
    for (int t = 0; t < 4; t++) {
        int cur = t & 1, nxt = cur ^ 1;
        if (t + 1 < 4) {
            int k0 = (t + 1) * 16;
            ra0 = *(const float4*)(Ap + k0 + 0);
            ra1 = *(const float4*)(Ap + k0 + 4);
            rb0 = *(const float4*)&B[(size_t)(kbase + k0 + kkB0) * 64 + nnB];
            rb1 = *(const float4*)&B[(size_t)(kbase + k0 + kkB0 + 8) * 64 + nnB];
        }
        #pragma unroll
        for (int k = 0; k < 16; k++) {
            float4 b4 = *(const float4*)&Bs[cur][k][tx * 4];
            float4 a0 = *(const float4*)&As[cur][k][ty * 8];
            float4 a1 = *(const float4*)&As[cur][k][ty * 8 + 4];
            float ar[8] = {a0.x, a0.y, a0.z, a0.w, a1.x, a1.y, a1.z, a1.w};
            #pragma unroll
            for (int i = 0; i < 8; i++) {
                c[i][0] += ar[i] * b4.x; c[i][1] += ar[i] * b4.y;
                c[i][2] += ar[i] * b4.z; c[i][3] += ar[i] * b4.w;
            }
        }
        if (t + 1 < 4) {
            As[nxt][aK0 + 0][aRow] = ra0.x; As[nxt][aK0 + 1][aRow] = ra0.y;
            As[nxt][aK0 + 2][aRow] = ra0.z; As[nxt][aK0 + 3][aRow] = ra0.w;
            As[nxt][aK0 + 4][aRow] = ra1.x; As[nxt][aK0 + 5][aRow] = ra1.y;
            As[nxt][aK0 + 6][aRow] = ra1.z; As[nxt][aK0 + 7][aRow] = ra1.w;
            *(float4*)&Bs[nxt][kkB0][nnB] = rb0;
            *(float4*)&Bs[nxt][kkB0 + 8][nnB] = rb1;
        }
        __syncthreads();
    }
    #pragma unroll
    for (int i = 0; i < 8; i++) {
        float4 v = make_float4(c[i][0], c[i][1], c[i][2], c[i][3]);
        *(float4*)&Cb[(size_t)(m0 + ty * 8 + i) * 64 + tx * 4] = v;
    }
}

// ---------------- layer2 reduce partials + scores + fp16 table -----------------
__global__ void reduce_scores2(const float* __restrict__ part, const float* __restrict__ a,
                               __half* __restrict__ h2h, float* __restrict__ s1,
                               float* __restrict__ s2) {
    int row = blockIdx.x;
    int d = threadIdx.x;            // 64 threads
    grid_dep_wait();
    size_t off = (size_t)row * 64 + d;
    float v = 0.f;
    #pragma unroll
    for (int z = 0; z < 8; z++) v += part[off + (size_t)z * NN64];
    h2h[off] = __float2half_rn(v);
    float p1 = v * a[d];
    float p2 = v * a[64 + d];
    #pragma unroll
    for (int o = 16; o > 0; o >>= 1) {
        p1 += __shfl_xor_sync(0xffffffffu, p1, o);
        p2 += __shfl_xor_sync(0xffffffffu, p2, o);
    }
    __shared__ float r1[2], r2[2];
    if ((d & 31) == 0) { r1[d >> 5] = p1; r2[d >> 5] = p2; }
    __syncthreads();
    if (d == 0) { s1[row] = r1[0] + r1[1]; s2[row] = r2[0] + r2[1]; }
}

// ---------------- layer2 attention: warp per row, fp16 gather ------------------
__global__ void att2_kernel(const __half2* __restrict__ hh, const float* __restrict__ s1,
                            const float* __restrict__ s2, const int* __restrict__ cnt,
                            const int* __restrict__ idx, float* __restrict__ out) {
    int wr   = threadIdx.x >> 5;     // 8 warps
    int lane = threadIdx.x & 31;
    int row  = blockIdx.x * 8 + wr;

    __shared__ int   s_nbr[8][MAXDEG];
    __shared__ float s_w[8][MAXDEG];

    grid_dep_wait();

    int n = cnt[row];
    const int* ip = idx + row * MAXDEG;
    for (int i = lane; i < n; i += 32) s_nbr[wr][i] = ip[i];
    __syncwarp();

    float s1i = s1[row];

    float mx = -3.0e38f;
    for (int i = lane; i < n; i += 32) mx = fmaxf(mx, s2[s_nbr[wr][i]]);
    #pragma unroll
    for (int o = 16; o > 0; o >>= 1) mx = fmaxf(mx, __shfl_xor_sync(0xffffffffu, mx, o));
    float m = lrelu(s1i + mx);

    float zp = 0.f;
    for (int i = lane; i < n; i += 32) {
        float e = lrelu(s1i + s2[s_nbr[wr][i]]);
        float w = __expf(e - m);
        s_w[wr][i] = w;
        zp += w;
    }
    #pragma unroll
    for (int o = 16; o > 0; o >>= 1) zp += __shfl_xor_sync(0xffffffffu, zp, o);
    __syncwarp();

    float2 acc = make_float2(0.f, 0.f);
    int i = 0;
    for (; i + 3 < n; i += 4) {
        float w0 = s_w[wr][i],     w1 = s_w[wr][i + 1];
        float w2 = s_w[wr][i + 2], w3 = s_w[wr][i + 3];
        float2 v0 = __half22float2(hh[(size_t)s_nbr[wr][i]     * 32 + lane]);
        float2 v1 = __half22float2(hh[(size_t)s_nbr[wr][i + 1] * 32 + lane]);
        float2 v2 = __half22float2(hh[(size_t)s_nbr[wr][i + 2] * 32 + lane]);
        float2 v3 = __half22float2(hh[(size_t)s_nbr[wr][i + 3] * 32 + lane]);
        acc.x += w0 * v0.x; acc.y += w0 * v0.y;
        acc.x += w1 * v1.x; acc.y += w1 * v1.y;
        acc.x += w2 * v2.x; acc.y += w2 * v2.y;
        acc.x += w3 * v3.x; acc.y += w3 * v3.y;
    }
    for (; i < n; i++) {
        float w = s_w[wr][i];
        float2 v = __half22float2(hh[(size_t)s_nbr[wr][i] * 32 + lane]);
        acc.x += w * v.x; acc.y += w * v.y;
    }
    float inv = 1.f / zp;
    ((float2*)out)[(size_t)row * 32 + lane] = make_float2(acc.x * inv, acc.y * inv);
}

// ---------------- launcher ----------------
template <typename... Args>
static void launch_pdl(void (*kern)(Args...), dim3 grid, dim3 block,
                       cudaStream_t s, Args... args) {
    cudaLaunchConfig_t cfg = {};
    cfg.gridDim = grid; cfg.blockDim = block; cfg.stream = s;
    cudaLaunchAttribute at[1];
    at[0].id = cudaLaunchAttributeProgrammaticStreamSerialization;
    at[0].val.programmaticStreamSerializationAllowed = 1;
    cfg.attrs = at; cfg.numAttrs = 1;
    cudaLaunchKernelEx(&cfg, kern, args...);
}

extern "C" void kernel_launch(void* const* d_in, const int* in_sizes, int n_in,
                              void* d_out, int out_size) {
    const float* features = (const float*)d_in[0];   // [4096, 256]
    const float* adj      = (const float*)d_in[1];   // [4096, 4096]
    const float* W_heads  = (const float*)d_in[2];   // [8, 256, 64]
    const float* a_heads  = (const float*)d_in[3];   // [8, 128, 1]
    const float* W_out    = (const float*)d_in[4];   // [512, 64]
    const float* a_out    = (const float*)d_in[5];   // [128, 1]
    float* out = (float*)d_out;                      // [4096, 64]

    int    *cnt, *idxp;
    float  *s1a, *s2a, *x2, *h2p, *s1b, *s2b;
    __half *h1h, *h2h;
    cudaGetSymbolAddress((void**)&cnt,  g_cnt);
    cudaGetSymbolAddress((void**)&idxp, g_idx);
    cudaGetSymbolAddress((void**)&h1h,  g_h1h);
    cudaGetSymbolAddress((void**)&s1a,  g_s1a);
    cudaGetSymbolAddress((void**)&s2a,  g_s2a);
    cudaGetSymbolAddress((void**)&x2,   g_x2);
    cudaGetSymbolAddress((void**)&h2p,  g_h2p);
    cudaGetSymbolAddress((void**)&h2h,  g_h2h);
    cudaGetSymbolAddress((void**)&s1b,  g_s1b);
    cudaGetSymbolAddress((void**)&s2b,  g_s2b);

    // fork: build_csr (HBM-bound) concurrent with gemm_fused (FMA-bound)
    cudaStream_t sB;
    cudaStreamCreateWithFlags(&sB, cudaStreamNonBlocking);
    cudaEvent_t eF, eJ;
    cudaEventCreateWithFlags(&eF, cudaEventDisableTiming);
    cudaEventCreateWithFlags(&eJ, cudaEventDisableTiming);

    cudaEventRecord(eF, 0);
    cudaStreamWaitEvent(sB, eF, 0);
    build_csr<<<NNODES, 256, 0, sB>>>(adj, cnt, idxp);
    cudaEventRecord(eJ, sB);

    gemm_fused<<<dim3(32, 1, 8), 256>>>(features, W_heads, h1h, a_heads, s1a, s2a);

    cudaStreamWaitEvent(0, eJ, 0);   // join before att1

    att1_kernel<<<NNODES, 256>>>((const __half2*)h1h, s1a, s2a, cnt, idxp, x2);
    launch_pdl(gemm_splitk, dim3(64, 1, 8), dim3(128), (cudaStream_t)0,
               (const float*)x2, W_out, h2p);
    launch_pdl(reduce_scores2, dim3(NNODES), dim3(64), (cudaStream_t)0,
               (const float*)h2p, a_out, h2h, s1b, s2b);
    launch_pdl(att2_kernel, dim3(NNODES / 8), dim3(256), (cudaStream_t)0,
               (const __half2*)h2h, (const float*)s1b, (const float*)s2b,
               (const int*)cnt, (const int*)idxp, out);
}